// round 16
// baseline (speedup 1.0000x reference)
#include <cuda_runtime.h>
#include <cuda_bf16.h>
#include <cstdint>

// Problem constants (fixed by the reference)
#define B_SEG   16
#define D_F     128            // fine feature dim  (32 float4)
#define D_C     256            // coarse feature dim (64 float4)
#define D_OUT   (D_C + D_F)    // 384

// 148 groups of 8 CTAs = 1184 CTAs (one wave at occ 8).
// Each group co-sweeps ONE contiguous region (rows interleaved mod 8 across
// its 8 CTAs) -> 148 concurrent DRAM streams instead of 1184, for better
// row-buffer locality, while keeping 512B-coalesced warp loads.
#define NG_C    16             // coarse groups (CTAs 0..127)
#define NG_F    132            // fine groups   (CTAs 128..1183)
#define CTA_C   (NG_C * 8)     // 128
#define NBLK    ((NG_C + NG_F) * 8)   // 1184

// Self-restoring device state (zero at module load; each segment's last
// contributor finalizes that segment and resets its state).
__device__ float        g_scratch[B_SEG * D_OUT];
__device__ unsigned int g_segcnt[B_SEG];

// ---------------------------------------------------------------------------
// Specialized work loop. CTA owns rows {A+k, A+k+8, ...} < B.
// FCOLS float4/row, LANES row lanes, OBASE output column offset.
// ---------------------------------------------------------------------------
template<int FCOLS, int LANES, int OBASE>
__device__ __forceinline__
void run_path(const float4* __restrict__ feats,
              float* __restrict__ out,
              const int* scumC, const int* scumF,
              const unsigned int* sexp,
              float4* shred, bool* sfin,
              int A, int B, int k) {
    const int tid = threadIdx.x;
    const int c   = tid % FCOLS;
    const int rr  = tid / FCOLS;
    const int* scum = (OBASE == 0) ? scumC : scumF;
    const float4* base = feats + c;

    const int rbeg = A + k;
    int s = 0;
    while (scum[s + 1] <= rbeg) ++s;

    int cur = rbeg;                    // next unconsumed CTA row (== rbeg mod 8)
    while (cur < B) {
        int e = scum[s + 1]; if (e > B) e = B;
        if (cur < e) {
            float4 acc = make_float4(0.f, 0.f, 0.f, 0.f);
#pragma unroll 4
            for (int r = cur + 8 * rr; r < e; r += 8 * LANES) {
                float4 v = __ldcs(base + (size_t)r * FCOLS);
                acc.x += v.x; acc.y += v.y; acc.z += v.z; acc.w += v.w;
            }

            // ---- block flush of this segment run ----
            shred[tid] = acc;
            __syncthreads();
            if (rr == 0) {
                float4 t = shred[c];
#pragma unroll
                for (int kk = 1; kk < LANES; ++kk) {
                    float4 w = shred[kk * FCOLS + c];
                    t.x += w.x; t.y += w.y; t.z += w.z; t.w += w.w;
                }
                float* o = g_scratch + s * D_OUT + OBASE + c * 4;
                atomicAdd(o + 0, t.x);
                atomicAdd(o + 1, t.y);
                atomicAdd(o + 2, t.z);
                atomicAdd(o + 3, t.w);
            }
            __threadfence();           // release our sums before counter bump
            __syncthreads();

            // ---- per-segment counter; last contributor finalizes ----
            if (tid == 0) {
                unsigned int expected = sexp[s];
                unsigned int old = atomicAdd(&g_segcnt[s], 1u);
                *sfin = (old == expected - 1u);
            }
            __syncthreads();

            if (*sfin) {
                __threadfence();       // acquire: all contributors visible
                for (int i = tid; i < D_OUT; i += 256) {
                    int len = (i < D_C) ? (scumC[s + 1] - scumC[s])
                                        : (scumF[s + 1] - scumF[s]);
                    float v = __ldcg(&g_scratch[s * D_OUT + i]);
                    out[s * D_OUT + i] = v / (float)len;
                    g_scratch[s * D_OUT + i] = 0.0f;
                }
                if (tid == 0) g_segcnt[s] = 0u;
            }
            __syncthreads();

            cur += ((e - cur + 7) >> 3) << 3;   // first CTA row >= e
        }
        ++s;
    }
}

__global__ __launch_bounds__(256, 8)
void pare_grp_kernel(const float4* __restrict__ feats_c,
                     const float4* __restrict__ feats_f,
                     const int* __restrict__ lengths_c,
                     const int* __restrict__ lengths_f,
                     float* __restrict__ out,
                     int n_c, int n_f) {
    __shared__ float4        shred[256];
    __shared__ int           scumC[B_SEG + 1];
    __shared__ int           scumF[B_SEG + 1];
    __shared__ unsigned int  sexp[B_SEG];
    __shared__ bool          sfin;
    const int tid  = threadIdx.x;
    const int lane = tid & 31;

    // ---- parallel prologue: both cumsums via warp-redundant shfl scans ----
    {
        int vc = (lane < B_SEG) ? __ldg(lengths_c + lane) : 0;
        int vf = (lane < B_SEG) ? __ldg(lengths_f + lane) : 0;
#pragma unroll
        for (int o = 1; o < B_SEG; o <<= 1) {
            int nc2 = __shfl_up_sync(0xFFFFFFFFu, vc, o);
            int nf2 = __shfl_up_sync(0xFFFFFFFFu, vf, o);
            if (lane >= o) { vc += nc2; vf += nf2; }
        }
        if (lane < B_SEG) { scumC[lane + 1] = vc; scumF[lane + 1] = vf; }
        if (lane == 0)    { scumC[0] = 0;        scumF[0] = 0; }
        __syncwarp();
    }

    // ---- warp 0: expected contributor count per segment (overlaps loads of
    //      other warps; consumed only after a later __syncthreads) ----
    if (tid < B_SEG) {
        const int s = tid;
        unsigned int exp = 0;
        // coarse groups
        const int c0 = scumC[s], c1 = scumC[s + 1];
        for (int g = 0; g < NG_C; ++g) {
            int A = (int)(((long long)g)       * n_c / NG_C);
            int Bb= (int)(((long long)(g + 1)) * n_c / NG_C);
            int lo = (c0 > A) ? c0 : A;
            int hi = (c1 < Bb) ? c1 : Bb;
            int L = hi - lo;
            if (L > 0) exp += (L < 8) ? (unsigned)L : 8u;
        }
        // fine groups
        const int f0 = scumF[s], f1 = scumF[s + 1];
        for (int g = 0; g < NG_F; ++g) {
            int A = (int)(((long long)g)       * n_f / NG_F);
            int Bb= (int)(((long long)(g + 1)) * n_f / NG_F);
            int lo = (f0 > A) ? f0 : A;
            int hi = (f1 < Bb) ? f1 : Bb;
            int L = hi - lo;
            if (L > 0) exp += (L < 8) ? (unsigned)L : 8u;
        }
        sexp[s] = exp;
    }
    __syncwarp();

    if (blockIdx.x < CTA_C) {
        const int g = blockIdx.x >> 3;
        const int k = blockIdx.x & 7;
        int A = (int)(((long long)g)       * n_c / NG_C);
        int B = (int)(((long long)(g + 1)) * n_c / NG_C);
        run_path<64, 4, 0>(feats_c, out, scumC, scumF, sexp, shred, &sfin,
                           A, B, k);
    } else {
        const int t = blockIdx.x - CTA_C;
        const int g = t >> 3;
        const int k = t & 7;
        int A = (int)(((long long)g)       * n_f / NG_F);
        int B = (int)(((long long)(g + 1)) * n_f / NG_F);
        run_path<32, 8, D_C>(feats_f, out, scumC, scumF, sexp, shred, &sfin,
                             A, B, k);
    }
}

// ---------------------------------------------------------------------------
extern "C" void kernel_launch(void* const* d_in, const int* in_sizes, int n_in,
                              void* d_out, int out_size) {
    const float* feats_f   = (const float*)d_in[0];   // [524288, 128]
    const float* feats_c   = (const float*)d_in[1];   // [32768, 256]
    const int*   lengths_f = (const int*)d_in[2];     // [16]
    const int*   lengths_c = (const int*)d_in[3];     // [16]
    float* out = (float*)d_out;                       // [16, 384]

    const int n_f = in_sizes[0] / D_F;   // total fine rows
    const int n_c = in_sizes[1] / D_C;   // total coarse rows

    pare_grp_kernel<<<NBLK, 256>>>((const float4*)feats_c,
                                   (const float4*)feats_f,
                                   lengths_c, lengths_f, out, n_c, n_f);
}

// round 17
// speedup vs baseline: 1.1345x; 1.1345x over previous
#include <cuda_runtime.h>
#include <cuda_bf16.h>
#include <cstdint>

// Problem constants (fixed by the reference)
#define B_SEG   16
#define D_F     128            // fine feature dim  (32 float4)
#define D_C     256            // coarse feature dim (64 float4)
#define D_OUT   (D_C + D_F)    // 384

// Exactly one full wave on 148 SMs at occupancy 8: 148*8 = 1184 CTAs.
// Byte-balanced split: coarse tile ~248KB, fine tile ~249KB.
#define NT_C    132            // coarse tiles
#define NT_F    1052           // fine tiles
#define NBLK    (NT_C + NT_F)  // 1184

// Self-restoring device state (zero at module load; each segment's last
// contributor finalizes that segment and resets its state, so every graph
// replay sees zeros again).
__device__ float        g_scratch[B_SEG * D_OUT];
__device__ unsigned int g_segcnt[B_SEG];

// Tile index containing global row r for a tiling of n rows into NT tiles
// with boundaries floor(t*n/NT).
__device__ __forceinline__ int tile_of(int r, int NT, long long n) {
    return (int)(((long long)(r + 1) * NT - 1) / n);
}

// ---------------------------------------------------------------------------
// Specialized work loop: FCOLS float4 per row, LANES row lanes, OBASE output
// column offset. All addressing is 32-bit (max float4 index 16.7M < 2^31),
// strides are compile-time constants.
// ---------------------------------------------------------------------------
template<int FCOLS, int LANES, int OBASE>
__device__ __forceinline__
void run_path(const float4* __restrict__ feats,
              float* __restrict__ out,
              const int* scumC, const int* scumF,
              float4* shred, bool* sfin,
              int r0, int r1, int n_c, int n_f) {
    const int tid = threadIdx.x;
    const int c   = tid % FCOLS;
    const int rr  = tid / FCOLS;
    const int* scum = (OBASE == 0) ? scumC : scumF;
    const float4* base = feats + c;

    int s = 0;
    while (scum[s + 1] <= r0) ++s;

    while (r0 < r1) {
        int e = scum[s + 1]; if (e > r1) e = r1;

        float4 acc = make_float4(0.f, 0.f, 0.f, 0.f);
        {
            // 32-bit float4-unit indexing: idx < 16.8M always
            int idx  = (r0 + rr) * FCOLS;
            int iend = e * FCOLS;
#pragma unroll 4
            for (; idx < iend; idx += LANES * FCOLS) {
                float4 v = __ldcs(base + idx);
                acc.x += v.x; acc.y += v.y; acc.z += v.z; acc.w += v.w;
            }
        }

        // ---- block flush of this segment run ----
        shred[tid] = acc;
        __syncthreads();
        if (rr == 0) {
            float4 t = shred[c];
#pragma unroll
            for (int k = 1; k < LANES; ++k) {
                float4 w = shred[k * FCOLS + c];
                t.x += w.x; t.y += w.y; t.z += w.z; t.w += w.w;
            }
            float* o = g_scratch + s * D_OUT + OBASE + c * 4;
            atomicAdd(o + 0, t.x);
            atomicAdd(o + 1, t.y);
            atomicAdd(o + 2, t.z);
            atomicAdd(o + 3, t.w);
        }
        __threadfence();   // release our sums before the counter bump
        __syncthreads();

        // ---- per-segment completion counter; last contributor finalizes ----
        if (tid == 0) {
            int cA = tile_of(scumC[s + 1] - 1, NT_C, n_c)
                   - tile_of(scumC[s],         NT_C, n_c) + 1;
            int cB = tile_of(scumF[s + 1] - 1, NT_F, n_f)
                   - tile_of(scumF[s],         NT_F, n_f) + 1;
            unsigned int expected = (unsigned int)(cA + cB);
            unsigned int old = atomicAdd(&g_segcnt[s], 1u);
            *sfin = (old == expected - 1u);
        }
        __syncthreads();

        if (*sfin) {
            __threadfence();   // acquire: all contributors' atomics visible
            for (int i = tid; i < D_OUT; i += 256) {
                int len = (i < D_C) ? (scumC[s + 1] - scumC[s])
                                    : (scumF[s + 1] - scumF[s]);
                float v = __ldcg(&g_scratch[s * D_OUT + i]);
                out[s * D_OUT + i] = v / (float)len;
                g_scratch[s * D_OUT + i] = 0.0f;
            }
            if (tid == 0) g_segcnt[s] = 0u;
        }
        __syncthreads();

        r0 = e; ++s;
    }
}

__global__ __launch_bounds__(256, 8)
void pare_fused_kernel(const float4* __restrict__ feats_c,
                       const float4* __restrict__ feats_f,
                       const int* __restrict__ lengths_c,
                       const int* __restrict__ lengths_f,
                       float* __restrict__ out,
                       int n_c, int n_f) {
    __shared__ float4 shred[256];
    __shared__ int    scumC[B_SEG + 1];
    __shared__ int    scumF[B_SEG + 1];
    __shared__ bool   sfin;
    const int tid  = threadIdx.x;
    const int lane = tid & 31;

    // ---- parallel prologue: both cumsums via warp shfl scans ----
    {
        int vc = (lane < B_SEG) ? __ldg(lengths_c + lane) : 0;
        int vf = (lane < B_SEG) ? __ldg(lengths_f + lane) : 0;
#pragma unroll
        for (int o = 1; o < B_SEG; o <<= 1) {
            int nc2 = __shfl_up_sync(0xFFFFFFFFu, vc, o);
            int nf2 = __shfl_up_sync(0xFFFFFFFFu, vf, o);
            if (lane >= o) { vc += nc2; vf += nf2; }
        }
        if (lane < B_SEG) { scumC[lane + 1] = vc; scumF[lane + 1] = vf; }
        if (lane == 0)    { scumC[0] = 0;        scumF[0] = 0; }
        __syncwarp();
    }

    if (blockIdx.x < NT_C) {
        const int t = blockIdx.x;
        int r0 = (int)(((long long)t)       * n_c / NT_C);
        int r1 = (int)(((long long)(t + 1)) * n_c / NT_C);
        run_path<64, 4, 0>(feats_c, out, scumC, scumF, shred, &sfin,
                           r0, r1, n_c, n_f);
    } else {
        const int t = blockIdx.x - NT_C;
        int r0 = (int)(((long long)t)       * n_f / NT_F);
        int r1 = (int)(((long long)(t + 1)) * n_f / NT_F);
        run_path<32, 8, D_C>(feats_f, out, scumC, scumF, shred, &sfin,
                             r0, r1, n_c, n_f);
    }
}

// ---------------------------------------------------------------------------
extern "C" void kernel_launch(void* const* d_in, const int* in_sizes, int n_in,
                              void* d_out, int out_size) {
    const float* feats_f   = (const float*)d_in[0];   // [524288, 128]
    const float* feats_c   = (const float*)d_in[1];   // [32768, 256]
    const int*   lengths_f = (const int*)d_in[2];     // [16]
    const int*   lengths_c = (const int*)d_in[3];     // [16]
    float* out = (float*)d_out;                       // [16, 384]

    const int n_f = in_sizes[0] / D_F;   // total fine rows
    const int n_c = in_sizes[1] / D_C;   // total coarse rows

    pare_fused_kernel<<<NBLK, 256>>>((const float4*)feats_c,
                                     (const float4*)feats_f,
                                     lengths_c, lengths_f, out, n_c, n_f);
}